// round 1
// baseline (speedup 1.0000x reference)
#include <cuda_runtime.h>
#include <stdint.h>

#define IN_F  4096
#define OUT_F 11008
#define BATCH 16
#define SPLITS 16
#define KCHUNK (IN_F / SPLITS)   // 256
#define OTILE 512
#define GTHREADS 128
#define CPT 4                    // output channels per thread

// Static device scratch (no allocations allowed in kernel_launch).
__device__ __align__(16) float g_xt[IN_F * BATCH];                  // x transposed: [k][b]
__device__ __align__(16) float g_partial[SPLITS * BATCH * OUT_F];   // [split][b][o]

// ---------------------------------------------------------------------------
// Kernel 1: transpose x[b][k] -> xt[k][b] so the 16 batch values of a given k
// are contiguous (consumed as packed f32x2 pairs by the GEMM).
// ---------------------------------------------------------------------------
__global__ void transpose_x_kernel(const float* __restrict__ x) {
    int k = blockIdx.x * blockDim.x + threadIdx.x;
    if (k >= IN_F) return;
#pragma unroll
    for (int b = 0; b < BATCH; b++)
        g_xt[k * BATCH + b] = x[b * IN_F + k];
}

// Packed 2-wide fp32 FMA (FFMA2) — only reachable via PTX fma.rn.f32x2.
__device__ __forceinline__ unsigned long long fma2(unsigned long long a,
                                                   unsigned long long b,
                                                   unsigned long long c) {
    unsigned long long d;
    asm("fma.rn.f32x2 %0, %1, %2, %3;" : "=l"(d) : "l"(a), "l"(b), "l"(c));
    return d;
}

// Duplicate one fp32 into both lanes of a 64-bit packed register.
__device__ __forceinline__ unsigned long long dup_f32(float f) {
    unsigned long long d;
    unsigned int u = __float_as_uint(f);
    asm("mov.b64 %0, {%1, %1};" : "=l"(d) : "r"(u));
    return d;
}

// ---------------------------------------------------------------------------
// Kernel 2: split-K GEMM. Each thread owns CPT=4 output channels and streams
// its int32 weight rows (int4 vectorized); the shared xt values are broadcast
// loads. Accumulators are f32x2 pairs over the 16 batches (8 regs/channel).
// ---------------------------------------------------------------------------
__global__ void __launch_bounds__(GTHREADS) gemm_kernel(const int* __restrict__ W) {
    const int s  = blockIdx.y;
    const int k0 = s * KCHUNK;

    int  o[CPT];
    bool valid[CPT];
    const int* wptr[CPT];
#pragma unroll
    for (int c = 0; c < CPT; c++) {
        o[c]     = blockIdx.x * OTILE + threadIdx.x + c * GTHREADS;
        valid[c] = (o[c] < OUT_F);
        wptr[c]  = W + (long)(valid[c] ? o[c] : 0) * IN_F + k0;
    }

    unsigned long long acc[CPT][BATCH / 2];
#pragma unroll
    for (int c = 0; c < CPT; c++)
#pragma unroll
        for (int j = 0; j < BATCH / 2; j++) acc[c][j] = 0ull;

    // xt viewed as packed f32x2 (double) pairs, offset to this K split.
    const double* xt = (const double*)g_xt + (long)k0 * (BATCH / 2);

    for (int k = 0; k < KCHUNK; k += 4) {
        // 4 consecutive k weights per channel, one LDG.128 each.
        int wq[CPT][4];
#pragma unroll
        for (int c = 0; c < CPT; c++)
            *(int4*)wq[c] = *(const int4*)(wptr[c] + k);

#pragma unroll
        for (int kk = 0; kk < 4; kk++) {
            // 16 batch values of x for this k, as 8 packed f32x2.
            unsigned long long xv[BATCH / 2];
            const double2* xp = (const double2*)(xt + (long)(k + kk) * (BATCH / 2));
#pragma unroll
            for (int j = 0; j < 4; j++) {
                double2 t = xp[j];
                xv[2 * j]     = __double_as_longlong(t.x);
                xv[2 * j + 1] = __double_as_longlong(t.y);
            }
#pragma unroll
            for (int c = 0; c < CPT; c++) {
                unsigned long long wp = dup_f32((float)wq[c][kk]);  // exact for |w|<=127
#pragma unroll
                for (int j = 0; j < BATCH / 2; j++)
                    acc[c][j] = fma2(wp, xv[j], acc[c][j]);
            }
        }
    }

    // Store partial sums (unique (s,b,o) per write -> deterministic, no atomics).
    float* pbase = g_partial + (long)s * (BATCH * OUT_F);
#pragma unroll
    for (int c = 0; c < CPT; c++) {
        if (!valid[c]) continue;
#pragma unroll
        for (int j = 0; j < BATCH / 2; j++) {
            unsigned long long a = acc[c][j];
            float lo = __uint_as_float((unsigned int)(a & 0xffffffffu));
            float hi = __uint_as_float((unsigned int)(a >> 32));
            pbase[(2 * j)     * OUT_F + o[c]] = lo;
            pbase[(2 * j + 1) * OUT_F + o[c]] = hi;
        }
    }
}

// ---------------------------------------------------------------------------
// Kernel 3: sum the SPLITS partials in a fixed order, apply scale and bias.
// ---------------------------------------------------------------------------
__global__ void reduce_kernel(const float* __restrict__ scale,
                              const float* __restrict__ bias,
                              float* __restrict__ out) {
    int e = blockIdx.x * blockDim.x + threadIdx.x;
    if (e >= BATCH * OUT_F) return;
    int o = e % OUT_F;
    float sum = 0.f;
#pragma unroll
    for (int s = 0; s < SPLITS; s++)
        sum += g_partial[(long)s * (BATCH * OUT_F) + e];
    out[e] = fmaf(sum, scale[o], bias[o]);
}

extern "C" void kernel_launch(void* const* d_in, const int* in_sizes, int n_in,
                              void* d_out, int out_size) {
    const float* x     = (const float*)d_in[0];
    const int*   W     = (const int*)d_in[1];
    const float* scale = (const float*)d_in[2];
    const float* bias  = (const float*)d_in[3];
    float*       out   = (float*)d_out;

    transpose_x_kernel<<<(IN_F + 255) / 256, 256>>>(x);

    dim3 grid((OUT_F + OTILE - 1) / OTILE, SPLITS);
    gemm_kernel<<<grid, GTHREADS>>>(W);

    reduce_kernel<<<(BATCH * OUT_F + 255) / 256, 256>>>(scale, bias, out);
}

// round 2
// speedup vs baseline: 1.3422x; 1.3422x over previous
#include <cuda_runtime.h>
#include <stdint.h>

typedef unsigned long long ull;

#define IN_F  4096
#define OUT_F 11008
#define BATCH 16
#define SPLITS 16
#define KCHUNK (IN_F / SPLITS)      // 256
#define GTHREADS 128
#define CPT 2
#define OTILE (GTHREADS * CPT)      // 256, 43*256 == 11008 exactly

// Static device scratch (allocations are forbidden).
__device__ __align__(16) float g_partial[SPLITS * BATCH * OUT_F];   // [split][b][o]

// Packed 2-wide fp32 FMA — only reachable via PTX fma.rn.f32x2.
__device__ __forceinline__ ull fma2(ull a, ull b, ull c) {
    ull d;
    asm("fma.rn.f32x2 %0, %1, %2, %3;" : "=l"(d) : "l"(a), "l"(b), "l"(c));
    return d;
}

// Duplicate one fp32 into both halves of a packed f32x2 register pair.
__device__ __forceinline__ ull dup_f32(float f) {
    ull d;
    unsigned int u = __float_as_uint(f);
    asm("mov.b64 %0, {%1, %1};" : "=l"(d) : "r"(u));
    return d;
}

// Process 4 consecutive k values: weights wq0/wq1 (int[4] each), x from smem.
#define COMP4(kbase, wq0, wq1)                                              \
    do {                                                                    \
        _Pragma("unroll")                                                   \
        for (int kk = 0; kk < 4; kk++) {                                    \
            const double2* xp = (const double2*)sx + ((kbase) + kk) * 4;    \
            ull xv[8];                                                      \
            _Pragma("unroll")                                               \
            for (int j = 0; j < 4; j++) {                                   \
                double2 t = xp[j];                                          \
                xv[2 * j]     = __double_as_longlong(t.x);                  \
                xv[2 * j + 1] = __double_as_longlong(t.y);                  \
            }                                                               \
            ull p0 = dup_f32((float)(wq0)[kk]);                             \
            ull p1 = dup_f32((float)(wq1)[kk]);                             \
            _Pragma("unroll")                                               \
            for (int j = 0; j < 8; j++) {                                   \
                acc0[j] = fma2(p0, xv[j], acc0[j]);                         \
                acc1[j] = fma2(p1, xv[j], acc1[j]);                         \
            }                                                               \
        }                                                                   \
    } while (0)

// ---------------------------------------------------------------------------
// Split-K GEMM. CTA = 128 threads x 2 output channels = 256 outs (exact fit).
// x tile staged to smem once; weight stream double-buffered (DRAM decoupled).
// ---------------------------------------------------------------------------
__global__ void __launch_bounds__(GTHREADS) gemm_kernel(const int* __restrict__ W,
                                                        const float* __restrict__ x) {
    __shared__ __align__(16) float sx[KCHUNK * BATCH];   // [k][b], 16 KB

    const int s  = blockIdx.y;
    const int k0 = s * KCHUNK;

    // Cooperative load + transpose of the x K-slice (coalesced reads).
    for (int idx = threadIdx.x; idx < KCHUNK * BATCH; idx += GTHREADS) {
        int b = idx >> 8;              // KCHUNK == 256
        int k = idx & (KCHUNK - 1);
        sx[k * BATCH + b] = x[b * IN_F + k0 + k];
    }
    __syncthreads();

    const int o0 = blockIdx.x * OTILE + threadIdx.x;     // always < OUT_F (exact tiling)
    const int* w0p = W + (long)o0 * IN_F + k0;
    const int* w1p = w0p + (long)GTHREADS * IN_F;

    ull acc0[8], acc1[8];
#pragma unroll
    for (int j = 0; j < 8; j++) { acc0[j] = 0ull; acc1[j] = 0ull; }

    // Double-buffered weight stream: 8 k-values (2 int4) per channel per stage.
    int wa0[4], wa1[4], wb0[4], wb1[4];
    *(int4*)wa0 = *(const int4*)(w0p);
    *(int4*)wa1 = *(const int4*)(w1p);
    *(int4*)wb0 = *(const int4*)(w0p + 4);
    *(int4*)wb1 = *(const int4*)(w1p + 4);

    for (int k = 0; k < KCHUNK; k += 8) {
        int kp = (k + 8 < KCHUNK) ? (k + 8) : 0;   // clamped prefetch (no OOB)
        int na0[4], na1[4], nb0[4], nb1[4];
        *(int4*)na0 = *(const int4*)(w0p + kp);
        *(int4*)na1 = *(const int4*)(w1p + kp);
        *(int4*)nb0 = *(const int4*)(w0p + kp + 4);
        *(int4*)nb1 = *(const int4*)(w1p + kp + 4);

        COMP4(k, wa0, wa1);
        COMP4(k + 4, wb0, wb1);

#pragma unroll
        for (int j = 0; j < 4; j++) {
            wa0[j] = na0[j]; wa1[j] = na1[j];
            wb0[j] = nb0[j]; wb1[j] = nb1[j];
        }
    }

    // Store partials: unique (s,b,o) per write -> deterministic, coalesced in o.
    float* pb = g_partial + (long)s * (BATCH * OUT_F);
    const int o1 = o0 + GTHREADS;
#pragma unroll
    for (int j = 0; j < 8; j++) {
        float lo0 = __uint_as_float((unsigned int)(acc0[j] & 0xffffffffu));
        float hi0 = __uint_as_float((unsigned int)(acc0[j] >> 32));
        float lo1 = __uint_as_float((unsigned int)(acc1[j] & 0xffffffffu));
        float hi1 = __uint_as_float((unsigned int)(acc1[j] >> 32));
        pb[(2 * j) * OUT_F + o0]     = lo0;
        pb[(2 * j + 1) * OUT_F + o0] = hi0;
        pb[(2 * j) * OUT_F + o1]     = lo1;
        pb[(2 * j + 1) * OUT_F + o1] = hi1;
    }
}

// ---------------------------------------------------------------------------
// Reduce the SPLITS partials (fixed order), apply scale + bias. float4-wide.
// ---------------------------------------------------------------------------
__global__ void reduce_kernel(const float* __restrict__ scale,
                              const float* __restrict__ bias,
                              float* __restrict__ out) {
    const int NV = BATCH * OUT_F / 4;
    int e = blockIdx.x * blockDim.x + threadIdx.x;
    if (e >= NV) return;
    int o4 = e % (OUT_F / 4);

    float4 sum = make_float4(0.f, 0.f, 0.f, 0.f);
#pragma unroll
    for (int s = 0; s < SPLITS; s++) {
        float4 v = ((const float4*)g_partial)[(long)s * NV + e];
        sum.x += v.x; sum.y += v.y; sum.z += v.z; sum.w += v.w;
    }
    float4 sc = ((const float4*)scale)[o4];
    float4 bi = ((const float4*)bias)[o4];
    float4 r;
    r.x = fmaf(sum.x, sc.x, bi.x);
    r.y = fmaf(sum.y, sc.y, bi.y);
    r.z = fmaf(sum.z, sc.z, bi.z);
    r.w = fmaf(sum.w, sc.w, bi.w);
    ((float4*)out)[e] = r;
}

extern "C" void kernel_launch(void* const* d_in, const int* in_sizes, int n_in,
                              void* d_out, int out_size) {
    const float* x     = (const float*)d_in[0];
    const int*   W     = (const int*)d_in[1];
    const float* scale = (const float*)d_in[2];
    const float* bias  = (const float*)d_in[3];
    float*       out   = (float*)d_out;

    dim3 grid(OUT_F / OTILE, SPLITS);          // 43 x 16 = 688 CTAs
    gemm_kernel<<<grid, GTHREADS>>>(W, x);

    int nv = BATCH * OUT_F / 4;
    reduce_kernel<<<(nv + 255) / 256, 256>>>(scale, bias, out);
}